// round 1
// baseline (speedup 1.0000x reference)
#include <cuda_runtime.h>
#include <math.h>
#include <stdint.h>

// Problem constants
#define NN    30000      // nodes
#define NE    480000     // edges
#define HD    256        // feature/hidden dim
#define MPAD  30080      // 235 * 128, padded row count for GEMM tiling
#define KTOT  768        // concat K dim: x_aug | h | t1
#define NCOL  1024       // 4 gates * 256
#define NH    (NN * HD)

// ---------------- static device scratch (no allocations allowed) ----------------
__device__ float g_xaug[NN * HD];          // augmented x
__device__ float g_t1[NN * HD];            // cheb T1 term (shared across gates)
__device__ float g_deg[NN];                // degree -> dinv in place
__device__ float g_Acat[MPAD * KTOT];      // packed [x_aug | h | t1]; pad rows stay 0
__device__ float g_Wbig[KTOT * NCOL];      // packed weights
__device__ float g_Z[MPAD * NCOL];         // gate pre-activations
__device__ float g_relu[MPAD * HD];        // relu(h0); pad rows stay 0

__device__ __forceinline__ void atomic_add4(float4* p, float4 v) {
#if defined(__CUDA_ARCH__) && (__CUDA_ARCH__ >= 900)
    atomicAdd(p, v);
#else
    float* f = reinterpret_cast<float*>(p);
    atomicAdd(f + 0, v.x);
    atomicAdd(f + 1, v.y);
    atomicAdd(f + 2, v.z);
    atomicAdd(f + 3, v.w);
#endif
}

__device__ __forceinline__ float sigf(float x) { return 1.0f / (1.0f + expf(-x)); }

// ---------------- init: x_aug = x, t1 = 0, deg = 0 ----------------
__global__ __launch_bounds__(256) void k_init(const float* __restrict__ x) {
    int i = blockIdx.x * blockDim.x + threadIdx.x;   // over NN*64 float4
    if (i < NN * 64) {
        float4 v = reinterpret_cast<const float4*>(x)[i];
        reinterpret_cast<float4*>(g_xaug)[i] = v;
        reinterpret_cast<float4*>(g_t1)[i] = make_float4(0.f, 0.f, 0.f, 0.f);
        if (i < NN) g_deg[i] = 0.f;
    }
}

// ---------------- neighbor augmentation scatter ----------------
// x_aug[src[e]] += x[snid[e]]; x_aug[dst[e]] += x[dnid[e]]  (gather from ORIGINAL x)
__global__ __launch_bounds__(256) void k_scatter_aug(
    const float* __restrict__ x,
    const int* __restrict__ src, const int* __restrict__ dst,
    const int* __restrict__ snid, const int* __restrict__ dnid)
{
    int i = blockIdx.x * blockDim.x + threadIdx.x;   // over NE*64
    if (i >= NE * 64) return;
    int e = i >> 6;
    int j = i & 63;
    const float4* x4 = reinterpret_cast<const float4*>(x);
    float4* a4 = reinterpret_cast<float4*>(g_xaug);
    float4 vs = x4[(size_t)snid[e] * 64 + j];
    atomic_add4(&a4[(size_t)src[e] * 64 + j], vs);
    float4 vd = x4[(size_t)dnid[e] * 64 + j];
    atomic_add4(&a4[(size_t)dst[e] * 64 + j], vd);
}

// ---------------- degree sum over src ----------------
__global__ __launch_bounds__(256) void k_deg(const int* __restrict__ src,
                                             const float* __restrict__ ew) {
    int e = blockIdx.x * blockDim.x + threadIdx.x;
    if (e < NE) atomicAdd(&g_deg[src[e]], ew[e]);
}

// ---------------- deg -> dinv in place ----------------
__global__ __launch_bounds__(256) void k_dinv() {
    int i = blockIdx.x * blockDim.x + threadIdx.x;
    if (i < NN) {
        float d = g_deg[i];
        g_deg[i] = (d > 0.f) ? rsqrtf(fmaxf(d, 1e-12f)) : 0.f;
    }
}

// ---------------- cheb T1 scatter: t1[dst] += norm * h[src] ----------------
__global__ __launch_bounds__(256) void k_t1(
    const float* __restrict__ h,
    const int* __restrict__ src, const int* __restrict__ dst,
    const float* __restrict__ ew)
{
    int i = blockIdx.x * blockDim.x + threadIdx.x;   // over NE*64
    if (i >= NE * 64) return;
    int e = i >> 6;
    int j = i & 63;
    int s = src[e], d = dst[e];
    float coef = -g_deg[s] * ew[e] * g_deg[d];
    const float4* h4 = reinterpret_cast<const float4*>(h);
    float4 hv = h4[(size_t)s * 64 + j];
    float4* t4 = reinterpret_cast<float4*>(g_t1);
    atomic_add4(&t4[(size_t)d * 64 + j],
                make_float4(coef * hv.x, coef * hv.y, coef * hv.z, coef * hv.w));
}

// ---------------- pack big weight matrix [768 x 1024] ----------------
// rows 0..255: W_g (D x H input weights); 256..511: Wc_g[0]; 512..767: Wc_g[1]
// cols: gate g in {i,f,g,o} occupies [g*256, g*256+256)
__global__ __launch_bounds__(256) void k_packW(
    const float* __restrict__ Wi, const float* __restrict__ Wf,
    const float* __restrict__ Wg, const float* __restrict__ Wo,
    const float* __restrict__ Wci, const float* __restrict__ Wcf,
    const float* __restrict__ Wcg, const float* __restrict__ Wco)
{
    int idx = blockIdx.x * blockDim.x + threadIdx.x;
    if (idx >= KTOT * NCOL) return;
    int k = idx >> 10;
    int col = idx & 1023;
    int g = col >> 8;
    int j = col & 255;
    const float* Win[4] = {Wi, Wf, Wg, Wo};
    const float* Wc[4]  = {Wci, Wcf, Wcg, Wco};
    float v;
    if (k < 256)       v = Win[g][k * 256 + j];
    else if (k < 512)  v = Wc[g][(k - 256) * 256 + j];
    else               v = Wc[g][65536 + (k - 512) * 256 + j];
    g_Wbig[idx] = v;
}

// ---------------- pack A = [x_aug | h | t1], float4 granularity ----------------
__global__ __launch_bounds__(256) void k_packA(const float* __restrict__ h) {
    int i = blockIdx.x * blockDim.x + threadIdx.x;   // over NN*192 float4
    if (i >= NN * 192) return;
    int row = i / 192;
    int c = i % 192;
    float4 v;
    if (c < 64)       v = reinterpret_cast<const float4*>(g_xaug)[(size_t)row * 64 + c];
    else if (c < 128) v = reinterpret_cast<const float4*>(h)[(size_t)row * 64 + (c - 64)];
    else              v = reinterpret_cast<const float4*>(g_t1)[(size_t)row * 64 + (c - 128)];
    reinterpret_cast<float4*>(g_Acat)[(size_t)row * 192 + c] = v;
}

// ---------------- classic 128x128x16 register-tiled SGEMM ----------------
// C[M x N] = A[M x K] * B[K x N] (+ bias[N]); rows >= m_limit are not stored.
// Grid: (N/128, Mtiles), 256 threads, each computes 8x8.
__global__ __launch_bounds__(256) void k_sgemm(
    const float* __restrict__ A, const float* __restrict__ B, float* __restrict__ C,
    int N, int K, const float* __restrict__ bias, int m_limit)
{
    const int BM = 128, BN = 128, BK = 16, TM = 8, TN = 8;
    __shared__ float As[BK][BM];
    __shared__ float Bs[BK][BN];

    int tid = threadIdx.x;
    int tx = tid & 15;
    int ty = tid >> 4;

    const float* Ablk = A + (size_t)blockIdx.y * BM * K;
    const float* Bblk = B + (size_t)blockIdx.x * BN;

    int aRow = tid >> 2;          // 0..63 (+64 for second chunk)
    int aCol = (tid & 3) * 4;     // 0,4,8,12
    int bRow = tid >> 5;          // 0..7 (+8 for second chunk)
    int bCol = (tid & 31) * 4;

    float acc[TM][TN] = {};
    float regM[TM], regN[TN];

    for (int kt = 0; kt < K; kt += BK) {
#pragma unroll
        for (int r = 0; r < 2; r++) {
            int row = aRow + r * 64;
            float4 v = *reinterpret_cast<const float4*>(Ablk + (size_t)row * K + kt + aCol);
            As[aCol + 0][row] = v.x;
            As[aCol + 1][row] = v.y;
            As[aCol + 2][row] = v.z;
            As[aCol + 3][row] = v.w;
        }
#pragma unroll
        for (int r = 0; r < 2; r++) {
            int row = bRow + r * 8;
            float4 v = *reinterpret_cast<const float4*>(Bblk + (size_t)(kt + row) * N + bCol);
            *reinterpret_cast<float4*>(&Bs[row][bCol]) = v;
        }
        __syncthreads();
#pragma unroll
        for (int k = 0; k < BK; k++) {
#pragma unroll
            for (int i = 0; i < TM; i++) regM[i] = As[k][ty * TM + i];
#pragma unroll
            for (int j = 0; j < TN; j++) regN[j] = Bs[k][tx * TN + j];
#pragma unroll
            for (int i = 0; i < TM; i++)
#pragma unroll
                for (int j = 0; j < TN; j++)
                    acc[i][j] += regM[i] * regN[j];
        }
        __syncthreads();
    }

    int cRow0 = blockIdx.y * BM + ty * TM;
    int cCol0 = blockIdx.x * BN + tx * TN;
#pragma unroll
    for (int i = 0; i < TM; i++) {
        int row = cRow0 + i;
        if (row < m_limit) {
#pragma unroll
            for (int j = 0; j < TN; j += 4) {
                float4 v = make_float4(acc[i][j], acc[i][j + 1], acc[i][j + 2], acc[i][j + 3]);
                if (bias) {
                    v.x += bias[cCol0 + j + 0];
                    v.y += bias[cCol0 + j + 1];
                    v.z += bias[cCol0 + j + 2];
                    v.w += bias[cCol0 + j + 3];
                }
                *reinterpret_cast<float4*>(C + (size_t)row * N + cCol0 + j) = v;
            }
        }
    }
}

// ---------------- gate elementwise: produce h0, c_new, relu(h0) ----------------
__global__ __launch_bounds__(256) void k_gates(
    const float* __restrict__ c,
    const float* __restrict__ bci, const float* __restrict__ bcf,
    const float* __restrict__ bcg, const float* __restrict__ bco,
    const float* __restrict__ bi, const float* __restrict__ bf,
    const float* __restrict__ bg, const float* __restrict__ bo,
    const float* __restrict__ wci, const float* __restrict__ wcf,
    const float* __restrict__ wco,
    float* __restrict__ out)   // d_out base: [h_out | h0 | c_new]
{
    int idx = blockIdx.x * blockDim.x + threadIdx.x;
    if (idx >= NH) return;
    int row = idx >> 8;
    int j = idx & 255;
    const float* z = g_Z + (size_t)row * NCOL;
    float cv = c[idx];
    float ig = sigf(z[j]       + bci[j] + bi[j] + wci[j] * cv);
    float fg = sigf(z[256 + j] + bcf[j] + bf[j] + wcf[j] * cv);
    float gg = tanhf(z[512 + j] + bcg[j] + bg[j]);
    float cn = fg * cv + ig * gg;
    float og = sigf(z[768 + j] + bco[j] + bo[j] + wco[j] * cn);
    float h0 = og * tanhf(cn);
    out[NH + idx]     = h0;
    out[2 * NH + idx] = cn;
    g_relu[idx] = fmaxf(h0, 0.f);
}

// ---------------- launch ----------------
extern "C" void kernel_launch(void* const* d_in, const int* in_sizes, int n_in,
                              void* d_out, int out_size) {
    const float* x    = (const float*)d_in[0];
    const int*   ei   = (const int*)d_in[1];
    const float* ew   = (const float*)d_in[2];
    const float* h    = (const float*)d_in[3];
    const float* c    = (const float*)d_in[4];
    const int*   snid = (const int*)d_in[5];
    const int*   dnid = (const int*)d_in[6];
    const float* Wi   = (const float*)d_in[7];
    const float* Wf   = (const float*)d_in[8];
    const float* Wg   = (const float*)d_in[9];
    const float* Wo   = (const float*)d_in[10];
    const float* Wci  = (const float*)d_in[11];
    const float* Wcf  = (const float*)d_in[12];
    const float* Wcg  = (const float*)d_in[13];
    const float* Wco  = (const float*)d_in[14];
    const float* bci  = (const float*)d_in[15];
    const float* bcf  = (const float*)d_in[16];
    const float* bcg  = (const float*)d_in[17];
    const float* bco  = (const float*)d_in[18];

    // Disambiguate tail ordering via W_lin's size (65536 vs 256-elem vectors).
    const float *bi, *bf, *bg, *bo, *blin, *wci, *wcf, *wco, *Wlin;
    if (in_sizes[27] == 65536) {
        // setup_inputs dict order: b_i,b_f,b_g,b_o,b_lin, w_ci,w_cf,w_co, W_lin
        bi = (const float*)d_in[19]; bf = (const float*)d_in[20];
        bg = (const float*)d_in[21]; bo = (const float*)d_in[22];
        blin = (const float*)d_in[23];
        wci = (const float*)d_in[24]; wcf = (const float*)d_in[25];
        wco = (const float*)d_in[26];
        Wlin = (const float*)d_in[27];
    } else {
        // reference signature order: w_ci,w_cf,w_co, b_i..b_o, W_lin, b_lin
        wci = (const float*)d_in[19]; wcf = (const float*)d_in[20];
        wco = (const float*)d_in[21];
        bi = (const float*)d_in[22]; bf = (const float*)d_in[23];
        bg = (const float*)d_in[24]; bo = (const float*)d_in[25];
        Wlin = (const float*)d_in[26];
        blin = (const float*)d_in[27];
    }

    const int* src = ei;
    const int* dst = ei + NE;
    float* out = (float*)d_out;

    // Resolve device scratch symbol addresses once per call (host-side constant math,
    // no CUDA API calls besides kernel launches).
    k_init<<<(NN * 64 + 255) / 256, 256>>>(x);
    k_scatter_aug<<<(NE * 64) / 256, 256>>>(x, src, dst, snid, dnid);
    k_deg<<<(NE + 255) / 256, 256>>>(src, ew);
    k_dinv<<<(NN + 255) / 256, 256>>>();
    k_t1<<<(NE * 64) / 256, 256>>>(h, src, dst, ew);
    k_packW<<<(KTOT * NCOL) / 256, 256>>>(Wi, Wf, Wg, Wo, Wci, Wcf, Wcg, Wco);
    k_packA<<<(NN * 192) / 256, 256>>>(h);

    // Big fused GEMM: Z[30080 x 1024] = Acat[30080 x 768] @ Wbig[768 x 1024]
    {
        float* Zp;  float* Ap;  float* Wp;
        cudaGetSymbolAddress((void**)&Zp, g_Z);
        cudaGetSymbolAddress((void**)&Ap, g_Acat);
        cudaGetSymbolAddress((void**)&Wp, g_Wbig);
        dim3 grid(NCOL / 128, MPAD / 128);
        k_sgemm<<<grid, 256>>>(Ap, Wp, Zp, NCOL, KTOT, nullptr, MPAD);
    }

    k_gates<<<(NH + 255) / 256, 256>>>(c, bci, bcf, bcg, bco, bi, bf, bg, bo,
                                       wci, wcf, wco, out);

    // h_out = relu(h0) @ W_lin + b_lin
    {
        float* Rp;
        cudaGetSymbolAddress((void**)&Rp, g_relu);
        dim3 grid(HD / 128, MPAD / 128);
        k_sgemm<<<grid, 256>>>(Rp, Wlin, out, HD, HD, blin, NN);
    }
}

// round 3
// speedup vs baseline: 1.6810x; 1.6810x over previous
#include <cuda_runtime.h>
#include <cuda_bf16.h>
#include <math.h>
#include <stdint.h>

// Problem constants
#define NN    30000
#define NE    480000
#define HD    256
#define MPAD  30080      // 235*128
#define KTOT  768        // x_aug | h | t1
#define NCOL  1024       // 4 gates * 256
#define NH    (NN * HD)

// ---------------- static device scratch ----------------
__device__ float g_xaug[NN * HD];
__device__ float g_t1[NN * HD];
__device__ float g_deg[NN];
__device__ float g_Z[MPAD * NCOL];                    // gate pre-activations (fp32)
__device__ __align__(16) __nv_bfloat16 g_Ah[MPAD * KTOT];
__device__ __align__(16) __nv_bfloat16 g_Al[MPAD * KTOT];
__device__ __align__(16) __nv_bfloat16 g_Wh[NCOL * KTOT];   // W transposed: [n][k]
__device__ __align__(16) __nv_bfloat16 g_Wl[NCOL * KTOT];
__device__ __align__(16) __nv_bfloat16 g_Rh[MPAD * HD];     // relu(h0) split
__device__ __align__(16) __nv_bfloat16 g_Rl[MPAD * HD];
__device__ __align__(16) __nv_bfloat16 g_WlTh[HD * HD];     // W_lin transposed split
__device__ __align__(16) __nv_bfloat16 g_WlTl[HD * HD];

__device__ __forceinline__ float sigf(float x) { return 1.0f / (1.0f + expf(-x)); }

__device__ __forceinline__ uint32_t smem_u32(const void* p) {
    uint32_t a;
    asm("{ .reg .u64 t; cvta.to.shared.u64 t, %1; cvt.u32.u64 %0, t; }" : "=r"(a) : "l"(p));
    return a;
}

// ---------------- init ----------------
__global__ __launch_bounds__(256) void k_init(const float* __restrict__ x) {
    int i = blockIdx.x * blockDim.x + threadIdx.x;
    if (i < NN * 64) {
        float4 v = reinterpret_cast<const float4*>(x)[i];
        reinterpret_cast<float4*>(g_xaug)[i] = v;
        reinterpret_cast<float4*>(g_t1)[i] = make_float4(0.f, 0.f, 0.f, 0.f);
        if (i < NN) g_deg[i] = 0.f;
    }
}

// ---------------- neighbor augmentation scatter ----------------
__global__ __launch_bounds__(256) void k_scatter_aug(
    const float* __restrict__ x,
    const int* __restrict__ src, const int* __restrict__ dst,
    const int* __restrict__ snid, const int* __restrict__ dnid)
{
    int i = blockIdx.x * blockDim.x + threadIdx.x;
    if (i >= NE * 64) return;
    int e = i >> 6;
    int j = i & 63;
    const float4* x4 = reinterpret_cast<const float4*>(x);
    float4* a4 = reinterpret_cast<float4*>(g_xaug);
    float4 vs = x4[(size_t)snid[e] * 64 + j];
    atomicAdd(&a4[(size_t)src[e] * 64 + j], vs);
    float4 vd = x4[(size_t)dnid[e] * 64 + j];
    atomicAdd(&a4[(size_t)dst[e] * 64 + j], vd);
}

__global__ __launch_bounds__(256) void k_deg(const int* __restrict__ src,
                                             const float* __restrict__ ew) {
    int e = blockIdx.x * blockDim.x + threadIdx.x;
    if (e < NE) atomicAdd(&g_deg[src[e]], ew[e]);
}

__global__ __launch_bounds__(256) void k_dinv() {
    int i = blockIdx.x * blockDim.x + threadIdx.x;
    if (i < NN) {
        float d = g_deg[i];
        g_deg[i] = (d > 0.f) ? rsqrtf(fmaxf(d, 1e-12f)) : 0.f;
    }
}

__global__ __launch_bounds__(256) void k_t1(
    const float* __restrict__ h,
    const int* __restrict__ src, const int* __restrict__ dst,
    const float* __restrict__ ew)
{
    int i = blockIdx.x * blockDim.x + threadIdx.x;
    if (i >= NE * 64) return;
    int e = i >> 6;
    int j = i & 63;
    int s = src[e], d = dst[e];
    float coef = -g_deg[s] * ew[e] * g_deg[d];
    const float4* h4 = reinterpret_cast<const float4*>(h);
    float4 hv = h4[(size_t)s * 64 + j];
    float4* t4 = reinterpret_cast<float4*>(g_t1);
    atomicAdd(&t4[(size_t)d * 64 + j],
              make_float4(coef * hv.x, coef * hv.y, coef * hv.z, coef * hv.w));
}

// ---------------- fp32 -> bf16 hi/lo split helpers ----------------
__device__ __forceinline__ void split8(const float* v, uint4& hi4, uint4& lo4) {
    __nv_bfloat16 h[8], l[8];
#pragma unroll
    for (int t = 0; t < 8; t++) {
        h[t] = __float2bfloat16(v[t]);
        l[t] = __float2bfloat16(v[t] - __bfloat162float(h[t]));
    }
    hi4 = *reinterpret_cast<uint4*>(h);
    lo4 = *reinterpret_cast<uint4*>(l);
}

// A = [x_aug | h | t1] -> bf16 hi/lo, [MPAD x 768]; pad rows zero.
__global__ __launch_bounds__(256) void k_conv_A(const float* __restrict__ h) {
    int i = blockIdx.x * blockDim.x + threadIdx.x;   // over MPAD*96 (chunks of 8 elems)
    if (i >= MPAD * 96) return;
    int row = i / 96;
    int c8 = i % 96;
    uint4 hi4, li4;
    if (row < NN) {
        const float4* srcp;
        int cc = c8 & 31;
        if (c8 < 32)       srcp = reinterpret_cast<const float4*>(g_xaug) + (size_t)row * 64 + cc * 2;
        else if (c8 < 64)  srcp = reinterpret_cast<const float4*>(h) + (size_t)row * 64 + cc * 2;
        else               srcp = reinterpret_cast<const float4*>(g_t1) + (size_t)row * 64 + cc * 2;
        float v[8];
        float4 a = srcp[0], b = srcp[1];
        v[0]=a.x; v[1]=a.y; v[2]=a.z; v[3]=a.w; v[4]=b.x; v[5]=b.y; v[6]=b.z; v[7]=b.w;
        split8(v, hi4, li4);
    } else {
        hi4 = make_uint4(0,0,0,0); li4 = hi4;
    }
    reinterpret_cast<uint4*>(g_Ah)[i] = hi4;
    reinterpret_cast<uint4*>(g_Al)[i] = li4;
}

// W transposed pack: B_mma[n][k], n = gate*256 + j
__global__ __launch_bounds__(256) void k_conv_W(
    const float* __restrict__ Wi, const float* __restrict__ Wf,
    const float* __restrict__ Wg, const float* __restrict__ Wo,
    const float* __restrict__ Wci, const float* __restrict__ Wcf,
    const float* __restrict__ Wcg, const float* __restrict__ Wco)
{
    int i = blockIdx.x * blockDim.x + threadIdx.x;   // over NCOL*96
    if (i >= NCOL * 96) return;
    int n = i / 96;
    int kc = i % 96;
    int g = n >> 8, j = n & 255;
    const float* Win[4] = {Wi, Wf, Wg, Wo};
    const float* Wc[4]  = {Wci, Wcf, Wcg, Wco};
    float v[8];
#pragma unroll
    for (int t = 0; t < 8; t++) {
        int k = kc * 8 + t;
        if (k < 256)      v[t] = Win[g][k * 256 + j];
        else if (k < 512) v[t] = Wc[g][(k - 256) * 256 + j];
        else              v[t] = Wc[g][65536 + (k - 512) * 256 + j];
    }
    uint4 hi4, lo4;
    split8(v, hi4, lo4);
    reinterpret_cast<uint4*>(g_Wh)[i] = hi4;
    reinterpret_cast<uint4*>(g_Wl)[i] = lo4;
}

// W_lin transposed pack
__global__ __launch_bounds__(256) void k_conv_Wlin(const float* __restrict__ Wlin) {
    int i = blockIdx.x * blockDim.x + threadIdx.x;   // over 256*32
    if (i >= HD * 32) return;
    int n = i / 32;
    int kc = i % 32;
    float v[8];
#pragma unroll
    for (int t = 0; t < 8; t++) v[t] = Wlin[(kc * 8 + t) * 256 + n];
    uint4 hi4, lo4;
    split8(v, hi4, lo4);
    reinterpret_cast<uint4*>(g_WlTh)[i] = hi4;
    reinterpret_cast<uint4*>(g_WlTl)[i] = lo4;
}

// ============ bf16-split GEMM via mma.sync (sm_80+ path, runs on sm_100) ============
// C[M x Ncols] = (Ah+Al)[M x K] @ (Bh+Bl)^T, B stored [Ncols x K] row-major.
// CTA tile 128x128x32, 3-stage cp.async pipeline, 8 warps (2x4), warp tile 64x32.
#define BKG   32
#define NSTG  3
#define TSTR  80                  // smem row stride bytes (64B payload + 16B pad); 5*16B mod 8 => conflict-free
#define TILEB (128 * TSTR)        // 10240 B per tile
#define STAGEB (4 * TILEB)        // Ah, Al, Bh, Bl
#define SMEM_GEMM (NSTG * STAGEB) // 122880 B

__device__ __forceinline__ void cp16(uint32_t saddr, const void* gaddr) {
    asm volatile("cp.async.cg.shared.global [%0], [%1], 16;" :: "r"(saddr), "l"(gaddr));
}
__device__ __forceinline__ void ldm_x4(uint32_t* r, uint32_t a) {
    asm volatile("ldmatrix.sync.aligned.m8n8.x4.shared.b16 {%0,%1,%2,%3}, [%4];"
                 : "=r"(r[0]), "=r"(r[1]), "=r"(r[2]), "=r"(r[3]) : "r"(a));
}
__device__ __forceinline__ void ldm_x2(uint32_t* r, uint32_t a) {
    asm volatile("ldmatrix.sync.aligned.m8n8.x2.shared.b16 {%0,%1}, [%2];"
                 : "=r"(r[0]), "=r"(r[1]) : "r"(a));
}
__device__ __forceinline__ void mma16816(float* c, const uint32_t* a, const uint32_t* b) {
    asm volatile(
        "mma.sync.aligned.m16n8k16.row.col.f32.bf16.bf16.f32 "
        "{%0,%1,%2,%3}, {%4,%5,%6,%7}, {%8,%9}, {%0,%1,%2,%3};"
        : "+f"(c[0]), "+f"(c[1]), "+f"(c[2]), "+f"(c[3])
        : "r"(a[0]), "r"(a[1]), "r"(a[2]), "r"(a[3]), "r"(b[0]), "r"(b[1]));
}

__global__ __launch_bounds__(256) void k_mma(
    const __nv_bfloat16* __restrict__ Ah, const __nv_bfloat16* __restrict__ Al,
    const __nv_bfloat16* __restrict__ Bh, const __nv_bfloat16* __restrict__ Bl,
    float* __restrict__ C, int K, int Ncols, const float* __restrict__ bias, int m_limit)
{
    extern __shared__ char smem[];
    const int tid = threadIdx.x;
    const int wid = tid >> 5;
    const int lane = tid & 31;
    const int m0 = blockIdx.y * 128;
    const int n0 = blockIdx.x * 128;
    const int nkt = K / BKG;
    const uint32_t sb = smem_u32(smem);

    const int wr = (wid >> 2) * 64;   // warp row offset within CTA tile
    const int wc = (wid & 3) * 32;    // warp col offset

    // per-thread cp.async chunk coords: 512 16B-chunks per tile, 2 per thread
    const int r0c = tid >> 2, c0c = tid & 3;            // chunk tid
    const int r1c = (tid + 256) >> 2, c1c = tid & 3;    // chunk tid+256

    float acc[4][4][4] = {};

    auto issue_stage = [&](int kt, int buf) {
        uint32_t s = sb + buf * STAGEB;
        const char* ahB = reinterpret_cast<const char*>(Ah);
        const char* alB = reinterpret_cast<const char*>(Al);
        const char* bhB = reinterpret_cast<const char*>(Bh);
        const char* blB = reinterpret_cast<const char*>(Bl);
        size_t kb = (size_t)kt * BKG * 2;   // byte offset of k-tile start within a row
        // chunk 0
        {
            size_t ga = ((size_t)(m0 + r0c) * K) * 2 + kb + c0c * 16;
            size_t gb = ((size_t)(n0 + r0c) * K) * 2 + kb + c0c * 16;
            uint32_t so = r0c * TSTR + c0c * 16;
            cp16(s + so, ahB + ga);
            cp16(s + TILEB + so, alB + ga);
            cp16(s + 2 * TILEB + so, bhB + gb);
            cp16(s + 3 * TILEB + so, blB + gb);
        }
        // chunk 1
        {
            size_t ga = ((size_t)(m0 + r1c) * K) * 2 + kb + c1c * 16;
            size_t gb = ((size_t)(n0 + r1c) * K) * 2 + kb + c1c * 16;
            uint32_t so = r1c * TSTR + c1c * 16;
            cp16(s + so, ahB + ga);
            cp16(s + TILEB + so, alB + ga);
            cp16(s + 2 * TILEB + so, bhB + gb);
            cp16(s + 3 * TILEB + so, blB + gb);
        }
    };

    // prologue: fill NSTG-1 stages
    for (int s = 0; s < NSTG - 1; s++) {
        if (s < nkt) issue_stage(s, s);
        asm volatile("cp.async.commit_group;");
    }

    for (int kt = 0; kt < nkt; kt++) {
        asm volatile("cp.async.wait_group %0;" :: "n"(NSTG - 2));
        __syncthreads();

        uint32_t s = sb + (kt % NSTG) * STAGEB;
        uint32_t sAh = s, sAl = s + TILEB, sBh = s + 2 * TILEB, sBl = s + 3 * TILEB;

#pragma unroll
        for (int ks = 0; ks < 2; ks++) {
            uint32_t ah[4][4], al[4][4], bh[4][2], bl[4][2];
            uint32_t aoff = (wr + (lane & 15)) * TSTR + ks * 32 + ((lane >> 4) & 1) * 16;
#pragma unroll
            for (int mt = 0; mt < 4; mt++) {
                ldm_x4(ah[mt], sAh + aoff + mt * 16 * TSTR);
                ldm_x4(al[mt], sAl + aoff + mt * 16 * TSTR);
            }
            int l = lane & 15;
            uint32_t boff = (wc + (l & 7)) * TSTR + ks * 32 + ((l >> 3) & 1) * 16;
#pragma unroll
            for (int nt = 0; nt < 4; nt++) {
                ldm_x2(bh[nt], sBh + boff + nt * 8 * TSTR);
                ldm_x2(bl[nt], sBl + boff + nt * 8 * TSTR);
            }
#pragma unroll
            for (int mt = 0; mt < 4; mt++)
#pragma unroll
                for (int nt = 0; nt < 4; nt++) {
                    mma16816(acc[mt][nt], ah[mt], bh[nt]);
                    mma16816(acc[mt][nt], ah[mt], bl[nt]);
                    mma16816(acc[mt][nt], al[mt], bh[nt]);
                }
        }
        __syncthreads();
        int nk = kt + NSTG - 1;
        if (nk < nkt) issue_stage(nk, nk % NSTG);
        asm volatile("cp.async.commit_group;");
    }

    // epilogue: direct register -> gmem
#pragma unroll
    for (int mt = 0; mt < 4; mt++) {
        int rA = m0 + wr + mt * 16 + (lane >> 2);
        int rB = rA + 8;
#pragma unroll
        for (int nt = 0; nt < 4; nt++) {
            int col = n0 + wc + nt * 8 + (lane & 3) * 2;
            float bx = 0.f, by = 0.f;
            if (bias) { bx = bias[col]; by = bias[col + 1]; }
            if (rA < m_limit) {
                float2 v = make_float2(acc[mt][nt][0] + bx, acc[mt][nt][1] + by);
                *reinterpret_cast<float2*>(C + (size_t)rA * Ncols + col) = v;
            }
            if (rB < m_limit) {
                float2 v = make_float2(acc[mt][nt][2] + bx, acc[mt][nt][3] + by);
                *reinterpret_cast<float2*>(C + (size_t)rB * Ncols + col) = v;
            }
        }
    }
}

// ---------------- gates: h0, c_new, relu split ----------------
__global__ __launch_bounds__(256) void k_gates(
    const float* __restrict__ c,
    const float* __restrict__ bci, const float* __restrict__ bcf,
    const float* __restrict__ bcg, const float* __restrict__ bco,
    const float* __restrict__ bi, const float* __restrict__ bf,
    const float* __restrict__ bg, const float* __restrict__ bo,
    const float* __restrict__ wci, const float* __restrict__ wcf,
    const float* __restrict__ wco,
    float* __restrict__ out)
{
    int idx = blockIdx.x * blockDim.x + threadIdx.x;
    if (idx >= MPAD * HD) return;
    int row = idx >> 8;
    int j = idx & 255;
    if (row >= NN) {
        g_Rh[idx] = __float2bfloat16(0.f);
        g_Rl[idx] = __float2bfloat16(0.f);
        return;
    }
    const float* z = g_Z + (size_t)row * NCOL;
    float cv = c[idx];
    float ig = sigf(z[j]       + bci[j] + bi[j] + wci[j] * cv);
    float fg = sigf(z[256 + j] + bcf[j] + bf[j] + wcf[j] * cv);
    float gg = tanhf(z[512 + j] + bcg[j] + bg[j]);
    float cn = fg * cv + ig * gg;
    float og = sigf(z[768 + j] + bco[j] + bo[j] + wco[j] * cn);
    float h0 = og * tanhf(cn);
    out[NH + idx]     = h0;
    out[2 * NH + idx] = cn;
    float r = fmaxf(h0, 0.f);
    __nv_bfloat16 rh = __float2bfloat16(r);
    __nv_bfloat16 rl = __float2bfloat16(r - __bfloat162float(rh));
    g_Rh[idx] = rh;
    g_Rl[idx] = rl;
}

// ---------------- launch ----------------
extern "C" void kernel_launch(void* const* d_in, const int* in_sizes, int n_in,
                              void* d_out, int out_size) {
    const float* x    = (const float*)d_in[0];
    const int*   ei   = (const int*)d_in[1];
    const float* ew   = (const float*)d_in[2];
    const float* h    = (const float*)d_in[3];
    const float* c    = (const float*)d_in[4];
    const int*   snid = (const int*)d_in[5];
    const int*   dnid = (const int*)d_in[6];
    const float* Wi   = (const float*)d_in[7];
    const float* Wf   = (const float*)d_in[8];
    const float* Wg   = (const float*)d_in[9];
    const float* Wo   = (const float*)d_in[10];
    const float* Wci  = (const float*)d_in[11];
    const float* Wcf  = (const float*)d_in[12];
    const float* Wcg  = (const float*)d_in[13];
    const float* Wco  = (const float*)d_in[14];
    const float* bci  = (const float*)d_in[15];
    const float* bcf  = (const float*)d_in[16];
    const float* bcg  = (const float*)d_in[17];
    const float* bco  = (const float*)d_in[18];

    const float *bi, *bf, *bg, *bo, *blin, *wci, *wcf, *wco, *Wlin;
    if (in_sizes[27] == 65536) {
        bi = (const float*)d_in[19]; bf = (const float*)d_in[20];
        bg = (const float*)d_in[21]; bo = (const float*)d_in[22];
        blin = (const float*)d_in[23];
        wci = (const float*)d_in[24]; wcf = (const float*)d_in[25];
        wco = (const float*)d_in[26];
        Wlin = (const float*)d_in[27];
    } else {
        wci = (const float*)d_in[19]; wcf = (const float*)d_in[20];
        wco = (const float*)d_in[21];
        bi = (const float*)d_in[22]; bf = (const float*)d_in[23];
        bg = (const float*)d_in[24]; bo = (const float*)d_in[25];
        Wlin = (const float*)d_in[26];
        blin = (const float*)d_in[27];
    }

    const int* src = ei;
    const int* dst = ei + NE;
    float* out = (float*)d_out;

    cudaFuncSetAttribute(k_mma, cudaFuncAttributeMaxDynamicSharedMemorySize, SMEM_GEMM);

    k_init<<<(NN * 64 + 255) / 256, 256>>>(x);
    k_conv_W<<<(NCOL * 96 + 255) / 256, 256>>>(Wi, Wf, Wg, Wo, Wci, Wcf, Wcg, Wco);
    k_conv_Wlin<<<(HD * 32 + 255) / 256, 256>>>(Wlin);
    k_scatter_aug<<<(NE * 64) / 256, 256>>>(x, src, dst, snid, dnid);
    k_deg<<<(NE + 255) / 256, 256>>>(src, ew);
    k_dinv<<<(NN + 255) / 256, 256>>>();
    k_t1<<<(NE * 64) / 256, 256>>>(h, src, dst, ew);
    k_conv_A<<<(MPAD * 96 + 255) / 256, 256>>>(h);

    float *Ah, *Al, *Wh, *Wl, *Zp, *Rh, *Rl, *WlTh, *WlTl;
    cudaGetSymbolAddress((void**)&Ah, g_Ah);
    cudaGetSymbolAddress((void**)&Al, g_Al);
    cudaGetSymbolAddress((void**)&Wh, g_Wh);
    cudaGetSymbolAddress((void**)&Wl, g_Wl);
    cudaGetSymbolAddress((void**)&Zp, g_Z);
    cudaGetSymbolAddress((void**)&Rh, g_Rh);
    cudaGetSymbolAddress((void**)&Rl, g_Rl);
    cudaGetSymbolAddress((void**)&WlTh, g_WlTh);
    cudaGetSymbolAddress((void**)&WlTl, g_WlTl);

    // big GEMM: Z[MPAD x 1024] = A @ W^T
    {
        dim3 grid(NCOL / 128, MPAD / 128);
        k_mma<<<grid, 256, SMEM_GEMM>>>(
            (const __nv_bfloat16*)Ah, (const __nv_bfloat16*)Al,
            (const __nv_bfloat16*)Wh, (const __nv_bfloat16*)Wl,
            Zp, KTOT, NCOL, nullptr, MPAD);
    }

    k_gates<<<(MPAD * HD + 255) / 256, 256>>>(c, bci, bcf, bcg, bco, bi, bf, bg, bo,
                                              wci, wcf, wco, out);

    // small GEMM: h_out[NN x 256] = relu(h0) @ W_lin + b_lin
    {
        dim3 grid(HD / 128, MPAD / 128);
        k_mma<<<grid, 256, SMEM_GEMM>>>(
            (const __nv_bfloat16*)Rh, (const __nv_bfloat16*)Rl,
            (const __nv_bfloat16*)WlTh, (const __nv_bfloat16*)WlTl,
            out, HD, HD, blin, NN);
    }
}